// round 5
// baseline (speedup 1.0000x reference)
#include <cuda_runtime.h>

#define NLVL   16
#define WIDTH  1000
#define PADW   (WIDTH + 4)     // w in [-2, 1001]
#define TPB    1024            // 32 warps, reg cap 64

typedef unsigned long long u64;
typedef unsigned int       u32;

// ---------------- packed f32x2 helpers ----------------
__device__ __forceinline__ u64 pk(float lo, float hi) {
    u64 r; asm("mov.b64 %0, {%1,%2};" : "=l"(r) : "f"(lo), "f"(hi)); return r;
}
__device__ __forceinline__ void upk(float& lo, float& hi, u64 v) {
    asm("mov.b64 {%0,%1}, %2;" : "=f"(lo), "=f"(hi) : "l"(v));
}
__device__ __forceinline__ u64 f2fma(u64 a, u64 b, u64 c) {
    u64 r; asm("fma.rn.f32x2 %0, %1, %2, %3;" : "=l"(r) : "l"(a), "l"(b), "l"(c)); return r;
}
__device__ __forceinline__ u64 f2mul(u64 a, u64 b) {
    u64 r; asm("mul.rn.f32x2 %0, %1, %2;" : "=l"(r) : "l"(a), "l"(b)); return r;
}
__device__ __forceinline__ u64 f2add(u64 a, u64 b) {
    u64 r; asm("add.rn.f32x2 %0, %1, %2;" : "=l"(r) : "l"(a), "l"(b)); return r;
}
__device__ __forceinline__ u64 f2sub(u64 a, u64 b) {
    u64 r; asm("sub.rn.f32x2 %0, %1, %2;" : "=l"(r) : "l"(a), "l"(b)); return r;
}
__device__ __forceinline__ u64 bc(float v) { return pk(v, v); }

// packed sin for two independent arguments (one lane-pair).
// 3-term Cody-Waite (exact split steps) + degree-11 odd poly.
// (-1)^k sign NOT applied; magic-biased k bits XORed into kacc so the caller
// applies the 3-sin product parity once.
__device__ __forceinline__ u64 psin(u64 a, u64& kacc,
                                    u64 INVPI, u64 MAGIC,
                                    u64 PIA, u64 PIB, u64 PIC,
                                    u64 C3, u64 C5, u64 C7, u64 C9, u64 C11) {
    u64 kb = f2fma(a, INVPI, MAGIC);   // rint via magic; mantissa LSB = k&1
    kacc  ^= kb;
    u64 k  = f2sub(kb, MAGIC);
    u64 r  = f2fma(k, PIA, a);
    r      = f2fma(k, PIB, r);
    r      = f2fma(k, PIC, r);
    u64 s  = f2mul(r, r);
    u64 p  = f2fma(C11, s, C9);
    p      = f2fma(p, s, C7);
    p      = f2fma(p, s, C5);
    p      = f2fma(p, s, C3);
    return f2fma(f2mul(p, s), r, r);
}

__global__ __launch_bounds__(TPB, 1)
void trig_hash_kernel(const float* __restrict__ x,
                      const float* __restrict__ grids,
                      const float* __restrict__ G,
                      const float* __restrict__ H,
                      float2* __restrict__ out,
                      int n_pairs)     // (B/2)*16
{
    extern __shared__ float2 gsm[];    // [(w+2)*16 + n] : bank pair = 2n

    // Stage grids (N,C,W) -> transposed padded smem. Zeros outside [0,W).
    for (int j = threadIdx.x; j < PADW * NLVL; j += TPB) {
        int n = j & (NLVL - 1);
        int w = (j >> 4) - 2;
        float c0 = 0.f, c1 = 0.f;
        if ((unsigned)w < (unsigned)WIDTH) {
            c0 = grids[(n * 2 + 0) * WIDTH + w];
            c1 = grids[(n * 2 + 1) * WIDTH + w];
        }
        gsm[j] = make_float2(c0, c1);
    }
    __syncthreads();

    const int gtid   = blockIdx.x * TPB + threadIdx.x;
    const int stride = gridDim.x * TPB;       // multiple of 16
    const int n      = gtid & (NLVL - 1);

    // Per-level constants in registers for the whole kernel.
    const u64 G00 = bc(G[  0 + n]), G01 = bc(G[ 16 + n]), G02 = bc(G[ 32 + n]);
    const u64 G10 = bc(G[ 48 + n]), G11 = bc(G[ 64 + n]), G12 = bc(G[ 80 + n]);
    const u64 G20 = bc(G[ 96 + n]), G21 = bc(G[112 + n]), G22 = bc(G[128 + n]);
    const u64 H0  = bc(H[  0 + n]), H1  = bc(H[ 16 + n]), H2  = bc(H[ 32 + n]);

    // Packed numeric constants (uniform -> UR file).
    const u64 INVPI = bc(0.3183098861837907f);
    const u64 MAGIC = bc(12582912.0f);                 // 1.5 * 2^23
    const u64 PIA   = bc(-3.140625f);
    const u64 PIB   = bc(-9.670257568359375e-4f);
    const u64 PIC   = bc(-6.2783296e-7f);
    const u64 C3    = bc(-1.6666667e-1f);
    const u64 C5    = bc( 8.3333333e-3f);
    const u64 C7    = bc(-1.9841270e-4f);
    const u64 C9    = bc( 2.7557319e-6f);
    const u64 C11   = bc(-2.5052108e-8f);
    const u64 ONEp  = bc(1.0f);
    const u64 K1Kp  = bc(1000.0f);
    const u64 NEG1p = bc(-1.0f);
    const u64 HALFp = bc(0.5f);
    const u64 NHLFp = bc(-0.5f);
    const u64 Cm075 = bc(-0.75f);
    const u64 C15   = bc(1.5f);
    const u64 C125  = bc(1.25f);
    const u64 Cm225 = bc(-2.25f);
    const u64 Cm125 = bc(-1.25f);
    const u64 C075  = bc(0.75f);

    u32 smbase;
    asm("{ .reg .u64 t; cvta.to.shared.u64 t, %1; cvt.u32.u64 %0, t; }"
        : "=r"(smbase) : "l"(gsm));
    // addr(tap0) = bits(bb)*128 + addrc   (0x4B400000*128 mod 2^32 = 0xA0000000)
    const u32 addrc = smbase + 128u + (u32)(n * 8) - 0xA0000000u;

    for (int p = gtid; p < n_pairs; p += stride) {
        const int g = p >> 4;                 // samples 2g, 2g+1
        const float2* xp = (const float2*)(x + 6 * g);
        float2 q0 = xp[0];                    // x0A x1A
        float2 q1 = xp[1];                    // x2A x0B
        float2 q2 = xp[2];                    // x1B x2B
        u64 X0 = pk(q0.x, q1.y);
        u64 X1 = pk(q0.y, q2.x);
        u64 X2 = pk(q1.x, q2.y);

        u64 a0 = f2fma(X0, G00, f2fma(X1, G10, f2fma(X2, G20, H0)));
        u64 a1 = f2fma(X0, G01, f2fma(X1, G11, f2fma(X2, G21, H1)));
        u64 a2 = f2fma(X0, G02, f2fma(X1, G12, f2fma(X2, G22, H2)));

        u64 kacc = 0;
        u64 s0 = psin(a0, kacc, INVPI, MAGIC, PIA, PIB, PIC, C3, C5, C7, C9, C11);
        u64 s1 = psin(a1, kacc, INVPI, MAGIC, PIA, PIB, PIC, C3, C5, C7, C9, C11);
        u64 s2 = psin(a2, kacc, INVPI, MAGIC, PIA, PIB, PIC, C3, C5, C7, C9, C11);
        u64 gx = f2mul(f2mul(s0, s1), s2);
        gx ^= (kacc & 0x0000000100000001ULL) << 31;   // product parity sign

        // ix chain, rounding-matched to reference: ((gx+1)*1000 - 1) * 0.5
        u64 t1  = f2add(gx, ONEp);
        u64 t2  = f2mul(t1, K1Kp);
        u64 t3  = f2add(t2, NEG1p);
        u64 ixm = f2fma(t3, HALFp, NHLFp);    // ix - 0.5 (exact)
        u64 bb  = f2add(ixm, MAGIC);          // MAGIC + floor(ix), int bits in mantissa
        u64 xf  = f2sub(bb, MAGIC);           // floor(ix)
        u64 xfn = xf ^ 0x8000000080000000ULL;
        u64 tp  = f2fma(t3, HALFp, xfn);      // t = ix - floor(ix), exact
        const u32 bbA = (u32)bb, bbB = (u32)(bb >> 32);

        // ---- issue all 8 tap loads up front (overlap LDS latency with weights) ----
        const u32 adA = bbA * 128u + addrc;
        const u32 adB = bbB * 128u + addrc;
        float a0x,a0y,a1x,a1y,a2x,a2y,a3x,a3y;
        float b0x,b0y,b1x,b1y,b2x,b2y,b3x,b3y;
        asm("ld.shared.v2.f32 {%0,%1},[%2];"     : "=f"(a0x), "=f"(a0y) : "r"(adA));
        asm("ld.shared.v2.f32 {%0,%1},[%2+128];" : "=f"(a1x), "=f"(a1y) : "r"(adA));
        asm("ld.shared.v2.f32 {%0,%1},[%2+256];" : "=f"(a2x), "=f"(a2y) : "r"(adA));
        asm("ld.shared.v2.f32 {%0,%1},[%2+384];" : "=f"(a3x), "=f"(a3y) : "r"(adA));
        asm("ld.shared.v2.f32 {%0,%1},[%2];"     : "=f"(b0x), "=f"(b0y) : "r"(adB));
        asm("ld.shared.v2.f32 {%0,%1},[%2+128];" : "=f"(b1x), "=f"(b1y) : "r"(adB));
        asm("ld.shared.v2.f32 {%0,%1},[%2+256];" : "=f"(b2x), "=f"(b2y) : "r"(adB));
        asm("ld.shared.v2.f32 {%0,%1},[%2+384];" : "=f"(b3x), "=f"(b3y) : "r"(adB));

        // ---- packed cubic-convolution weights (A in lo, B in hi) ----
        // w0 = ((-0.75t+1.5)t-0.75)t ; w1 = (1.25t-2.25)t^2+1
        // w2 = ((-1.25t+1.5)t+0.75)t ; w3 = (0.75t-0.75)t^2
        u64 pa = f2fma(Cm075, tp, C15);  pa = f2fma(pa, tp, Cm075);
        u64 W0 = f2mul(pa, tp);
        u64 pb = f2fma(C125, tp, Cm225);
        u64 W1 = f2fma(f2mul(pb, tp), tp, ONEp);
        u64 pc = f2fma(Cm125, tp, C15);  pc = f2fma(pc, tp, C075);
        u64 W2 = f2mul(pc, tp);
        u64 pd = f2fma(C075, tp, Cm075);
        u64 W3 = f2mul(f2mul(pd, tp), tp);

        float w0A,w0B,w1A,w1B,w2A,w2B,w3A,w3B;
        upk(w0A, w0B, W0); upk(w1A, w1B, W1);
        upk(w2A, w2B, W2); upk(w3A, w3B, W3);

        float accA0 = fmaf(a0x, w0A, fmaf(a1x, w1A, fmaf(a2x, w2A, a3x * w3A)));
        float accA1 = fmaf(a0y, w0A, fmaf(a1y, w1A, fmaf(a2y, w2A, a3y * w3A)));
        float accB0 = fmaf(b0x, w0B, fmaf(b1x, w1B, fmaf(b2x, w2B, b3x * w3B)));
        float accB1 = fmaf(b0y, w0B, fmaf(b1y, w1B, fmaf(b2y, w2B, b3y * w3B)));

        const int iA = (2 * g) * NLVL + n;    // out float2 index = s*16 + n
        out[iA]        = make_float2(accA0, accA1);
        out[iA + NLVL] = make_float2(accB0, accB1);
    }
}

extern "C" void kernel_launch(void* const* d_in, const int* in_sizes, int n_in,
                              void* d_out, int out_size)
{
    const float* x     = (const float*)d_in[0];
    const float* grids = (const float*)d_in[1];
    const float* G     = (const float*)d_in[2];
    const float* H     = (const float*)d_in[3];
    (void)n_in; (void)out_size;

    const int B       = in_sizes[0] / 3;
    const int n_pairs = (B / 2) * NLVL;

    const int smem_bytes = PADW * NLVL * (int)sizeof(float2);   // 128512

    cudaFuncSetAttribute(trig_hash_kernel,
                         cudaFuncAttributeMaxDynamicSharedMemorySize, smem_bytes);

    int sm_count = 148;
    cudaDeviceGetAttribute(&sm_count, cudaDevAttrMultiProcessorCount, 0);

    trig_hash_kernel<<<sm_count, TPB, smem_bytes>>>(
        x, grids, G, H, (float2*)d_out, n_pairs);
}

// round 6
// speedup vs baseline: 1.1426x; 1.1426x over previous
#include <cuda_runtime.h>

#define NLVL   16
#define WIDTH  1000
#define PADW   (WIDTH + 4)     // w in [-2, 1001]
#define TPB    1024            // 32 warps, reg cap 64

typedef unsigned long long u64;
typedef unsigned int       u32;

// ---------------- packed f32x2 helpers ----------------
__device__ __forceinline__ u64 pk(float lo, float hi) {
    u64 r; asm("mov.b64 %0, {%1,%2};" : "=l"(r) : "f"(lo), "f"(hi)); return r;
}
__device__ __forceinline__ void upk(float& lo, float& hi, u64 v) {
    asm("mov.b64 {%0,%1}, %2;" : "=f"(lo), "=f"(hi) : "l"(v));
}
__device__ __forceinline__ u64 f2fma(u64 a, u64 b, u64 c) {
    u64 r; asm("fma.rn.f32x2 %0, %1, %2, %3;" : "=l"(r) : "l"(a), "l"(b), "l"(c)); return r;
}
__device__ __forceinline__ u64 f2mul(u64 a, u64 b) {
    u64 r; asm("mul.rn.f32x2 %0, %1, %2;" : "=l"(r) : "l"(a), "l"(b)); return r;
}
__device__ __forceinline__ u64 f2sub(u64 a, u64 b) {
    u64 r; asm("sub.rn.f32x2 %0, %1, %2;" : "=l"(r) : "l"(a), "l"(b)); return r;
}
__device__ __forceinline__ u64 bc(float v) { return pk(v, v); }

// packed sin for two independent arguments (one lane-pair).
// 3-term Cody-Waite (exact split steps) + degree-11 odd poly.
// (-1)^k sign NOT applied; magic-biased k bits XORed into kacc so the caller
// applies the 3-sin product parity once.
__device__ __forceinline__ u64 psin(u64 a, u64& kacc,
                                    u64 INVPI, u64 MAGIC,
                                    u64 PIA, u64 PIB, u64 PIC,
                                    u64 C3, u64 C5, u64 C7, u64 C9, u64 C11) {
    u64 kb = f2fma(a, INVPI, MAGIC);   // rint via magic; mantissa LSB = k&1
    kacc  ^= kb;
    u64 k  = f2sub(kb, MAGIC);
    u64 r  = f2fma(k, PIA, a);
    r      = f2fma(k, PIB, r);
    r      = f2fma(k, PIC, r);
    u64 s  = f2mul(r, r);
    u64 p  = f2fma(C11, s, C9);
    p      = f2fma(p, s, C7);
    p      = f2fma(p, s, C5);
    p      = f2fma(p, s, C3);
    return f2fma(f2mul(p, s), r, r);
}

__global__ __launch_bounds__(TPB, 1)
void trig_hash_kernel(const float* __restrict__ x,
                      const float* __restrict__ grids,
                      const float* __restrict__ G,
                      const float* __restrict__ H,
                      float2* __restrict__ out,
                      int n_pairs)     // (B/2)*16
{
    extern __shared__ float2 gsm[];    // [(w+2)*16 + n] : bank pair = 2n

    // Stage grids (N,C,W) -> transposed padded smem. Zeros outside [0,W).
    for (int j = threadIdx.x; j < PADW * NLVL; j += TPB) {
        int n = j & (NLVL - 1);
        int w = (j >> 4) - 2;
        float c0 = 0.f, c1 = 0.f;
        if ((unsigned)w < (unsigned)WIDTH) {
            c0 = grids[(n * 2 + 0) * WIDTH + w];
            c1 = grids[(n * 2 + 1) * WIDTH + w];
        }
        gsm[j] = make_float2(c0, c1);
    }
    __syncthreads();

    const int gtid   = blockIdx.x * TPB + threadIdx.x;
    const int stride = gridDim.x * TPB;       // multiple of 16
    const int n      = gtid & (NLVL - 1);

    // Per-level constants in registers for the whole kernel.
    const u64 G00 = bc(G[  0 + n]), G01 = bc(G[ 16 + n]), G02 = bc(G[ 32 + n]);
    const u64 G10 = bc(G[ 48 + n]), G11 = bc(G[ 64 + n]), G12 = bc(G[ 80 + n]);
    const u64 G20 = bc(G[ 96 + n]), G21 = bc(G[112 + n]), G22 = bc(G[128 + n]);
    const u64 H0  = bc(H[  0 + n]), H1  = bc(H[ 16 + n]), H2  = bc(H[ 32 + n]);

    // Packed numeric constants.
    const u64 INVPI = bc(0.3183098861837907f);
    const u64 MAGIC = bc(12582912.0f);                 // 1.5 * 2^23
    const u64 PIA   = bc(-3.140625f);
    const u64 PIB   = bc(-9.670257568359375e-4f);
    const u64 PIC   = bc(-6.2783296e-7f);
    const u64 C3    = bc(-1.6666667e-1f);
    const u64 C5    = bc( 8.3333333e-3f);
    const u64 C7    = bc(-1.9841270e-4f);
    const u64 C9    = bc( 2.7557319e-6f);
    const u64 C11   = bc(-2.5052108e-8f);
    const u64 ONEp  = bc(1.0f);
    const u64 C500  = bc(500.0f);
    const u64 MAG499 = bc(12582912.0f + 499.0f);       // exact (< 2^24)
    const u64 C4995 = bc(499.5f);
    const u64 Cm075 = bc(-0.75f);
    const u64 C15   = bc(1.5f);
    const u64 C125  = bc(1.25f);
    const u64 Cm225 = bc(-2.25f);
    const u64 Cm125 = bc(-1.25f);
    const u64 C075  = bc(0.75f);

    u32 smbase;
    asm("{ .reg .u64 t; cvta.to.shared.u64 t, %1; cvt.u32.u64 %0, t; }"
        : "=r"(smbase) : "l"(gsm));
    // addr(tap0) = bits(bb)*128 + addrc   (0x4B400000*128 mod 2^32 = 0xA0000000)
    const u32 addrc = smbase + 128u + (u32)(n * 8) - 0xA0000000u;

    // ---- software pipeline: preload x for the first iteration ----
    float2 q0, q1, q2;
    {
        int p0 = (gtid < n_pairs) ? gtid : 0;
        const float2* xp = (const float2*)(x + 6 * (p0 >> 4));
        q0 = xp[0]; q1 = xp[1]; q2 = xp[2];
    }

    for (int p = gtid; p < n_pairs; p += stride) {
        // ---- prefetch next iteration's x (independent; hides DRAM latency) ----
        int pn = p + stride;
        int gn = ((pn < n_pairs) ? pn : p) >> 4;
        const float2* xn = (const float2*)(x + 6 * gn);
        float2 r0 = xn[0], r1 = xn[1], r2 = xn[2];

        // current pair: samples 2g (A), 2g+1 (B)
        u64 X0 = pk(q0.x, q1.y);
        u64 X1 = pk(q0.y, q2.x);
        u64 X2 = pk(q1.x, q2.y);

        u64 a0 = f2fma(X0, G00, f2fma(X1, G10, f2fma(X2, G20, H0)));
        u64 a1 = f2fma(X0, G01, f2fma(X1, G11, f2fma(X2, G21, H1)));
        u64 a2 = f2fma(X0, G02, f2fma(X1, G12, f2fma(X2, G22, H2)));

        u64 kacc = 0;
        u64 s0 = psin(a0, kacc, INVPI, MAGIC, PIA, PIB, PIC, C3, C5, C7, C9, C11);
        u64 s1 = psin(a1, kacc, INVPI, MAGIC, PIA, PIB, PIC, C3, C5, C7, C9, C11);
        u64 s2 = psin(a2, kacc, INVPI, MAGIC, PIA, PIB, PIC, C3, C5, C7, C9, C11);
        u64 gx = f2mul(f2mul(s0, s1), s2);
        gx ^= (kacc & 0x0000000100000001ULL) << 31;   // product parity sign

        // fused ix chain: ix = 500*gx + 499.5
        // bb = MAGIC + round(500*gx + 499)  (int bits in mantissa; ulp==1 in range)
        u64 bb = f2fma(gx, C500, MAG499);
        u64 xf = f2sub(bb, MAGIC);                    // float(base)
        u64 dd = f2sub(C4995, xf);                    // exact (halves < 1024)
        u64 tp = f2fma(gx, C500, dd);                 // t = ix - base, one rounding
        const u32 bbA = (u32)bb, bbB = (u32)(bb >> 32);

        // ---- issue all 8 tap loads up front ----
        const u32 adA = bbA * 128u + addrc;
        const u32 adB = bbB * 128u + addrc;
        float a0x,a0y,a1x,a1y,a2x,a2y,a3x,a3y;
        float b0x,b0y,b1x,b1y,b2x,b2y,b3x,b3y;
        asm("ld.shared.v2.f32 {%0,%1},[%2];"     : "=f"(a0x), "=f"(a0y) : "r"(adA));
        asm("ld.shared.v2.f32 {%0,%1},[%2+128];" : "=f"(a1x), "=f"(a1y) : "r"(adA));
        asm("ld.shared.v2.f32 {%0,%1},[%2+256];" : "=f"(a2x), "=f"(a2y) : "r"(adA));
        asm("ld.shared.v2.f32 {%0,%1},[%2+384];" : "=f"(a3x), "=f"(a3y) : "r"(adA));
        asm("ld.shared.v2.f32 {%0,%1},[%2];"     : "=f"(b0x), "=f"(b0y) : "r"(adB));
        asm("ld.shared.v2.f32 {%0,%1},[%2+128];" : "=f"(b1x), "=f"(b1y) : "r"(adB));
        asm("ld.shared.v2.f32 {%0,%1},[%2+256];" : "=f"(b2x), "=f"(b2y) : "r"(adB));
        asm("ld.shared.v2.f32 {%0,%1},[%2+384];" : "=f"(b3x), "=f"(b3y) : "r"(adB));

        // ---- packed cubic-convolution weights (A in lo, B in hi) ----
        u64 pa = f2fma(Cm075, tp, C15);  pa = f2fma(pa, tp, Cm075);
        u64 W0 = f2mul(pa, tp);
        u64 pb = f2fma(C125, tp, Cm225);
        u64 W1 = f2fma(f2mul(pb, tp), tp, ONEp);
        u64 pc = f2fma(Cm125, tp, C15);  pc = f2fma(pc, tp, C075);
        u64 W2 = f2mul(pc, tp);
        u64 pd = f2fma(C075, tp, Cm075);
        u64 W3 = f2mul(f2mul(pd, tp), tp);

        float w0A,w0B,w1A,w1B,w2A,w2B,w3A,w3B;
        upk(w0A, w0B, W0); upk(w1A, w1B, W1);
        upk(w2A, w2B, W2); upk(w3A, w3B, W3);

        float accA0 = fmaf(a0x, w0A, fmaf(a1x, w1A, fmaf(a2x, w2A, a3x * w3A)));
        float accA1 = fmaf(a0y, w0A, fmaf(a1y, w1A, fmaf(a2y, w2A, a3y * w3A)));
        float accB0 = fmaf(b0x, w0B, fmaf(b1x, w1B, fmaf(b2x, w2B, b3x * w3B)));
        float accB1 = fmaf(b0y, w0B, fmaf(b1y, w1B, fmaf(b2y, w2B, b3y * w3B)));

        const int iA = 2 * p - n;             // out float2 index = s*16 + n
        out[iA]        = make_float2(accA0, accA1);
        out[iA + NLVL] = make_float2(accB0, accB1);

        // rotate pipeline
        q0 = r0; q1 = r1; q2 = r2;
    }
}

extern "C" void kernel_launch(void* const* d_in, const int* in_sizes, int n_in,
                              void* d_out, int out_size)
{
    const float* x     = (const float*)d_in[0];
    const float* grids = (const float*)d_in[1];
    const float* G     = (const float*)d_in[2];
    const float* H     = (const float*)d_in[3];
    (void)n_in; (void)out_size;

    const int B       = in_sizes[0] / 3;
    const int n_pairs = (B / 2) * NLVL;

    const int smem_bytes = PADW * NLVL * (int)sizeof(float2);   // 128512

    cudaFuncSetAttribute(trig_hash_kernel,
                         cudaFuncAttributeMaxDynamicSharedMemorySize, smem_bytes);

    int sm_count = 148;
    cudaDeviceGetAttribute(&sm_count, cudaDevAttrMultiProcessorCount, 0);

    trig_hash_kernel<<<sm_count, TPB, smem_bytes>>>(
        x, grids, G, H, (float2*)d_out, n_pairs);
}

// round 8
// speedup vs baseline: 1.3085x; 1.1453x over previous
#include <cuda_runtime.h>

#define NLVL   16
#define WIDTH  1000
#define PADW   (WIDTH + 4)     // w in [-2, 1001]
#define TPB    1024

typedef unsigned long long u64;
typedef unsigned int       u32;

// ---------------- packed f32x2 helpers ----------------
__device__ __forceinline__ u64 pk(float lo, float hi) {
    u64 r; asm("mov.b64 %0, {%1,%2};" : "=l"(r) : "f"(lo), "f"(hi)); return r;
}
__device__ __forceinline__ void upk(float& lo, float& hi, u64 v) {
    asm("mov.b64 {%0,%1}, %2;" : "=f"(lo), "=f"(hi) : "l"(v));
}
__device__ __forceinline__ u64 f2fma(u64 a, u64 b, u64 c) {
    u64 r; asm("fma.rn.f32x2 %0, %1, %2, %3;" : "=l"(r) : "l"(a), "l"(b), "l"(c)); return r;
}
__device__ __forceinline__ u64 f2sub(u64 a, u64 b) {
    u64 r; asm("sub.rn.f32x2 %0, %1, %2;" : "=l"(r) : "l"(a), "l"(b)); return r;
}
__device__ __forceinline__ u64 bc(float v) { return pk(v, v); }

__device__ __forceinline__ float hwsin(float r) {   // r in [-pi, pi]
    float s; asm("sin.approx.f32 %0, %1;" : "=f"(s) : "f"(r)); return s;
}

// packed range reduction: r = a - 2*pi*rint(a/(2*pi)), exact CW split steps
__device__ __forceinline__ u64 pred2pi(u64 a, u64 INV2PI, u64 MAGIC,
                                       u64 NPIA, u64 NPIB, u64 NPIC) {
    u64 kb = f2fma(a, INV2PI, MAGIC);   // rint via magic
    u64 k  = f2sub(kb, MAGIC);
    u64 r  = f2fma(k, NPIA, a);         // -6.28125            (exact)
    r      = f2fma(k, NPIB, r);         // -1.934051513671875e-3 (exact)
    r      = f2fma(k, NPIC, r);         // -1.2556659e-6
    return r;
}

__global__ __launch_bounds__(TPB, 1)
void trig_hash_kernel(const float* __restrict__ x,
                      const float* __restrict__ grids,
                      const float* __restrict__ G,
                      const float* __restrict__ H,
                      float2* __restrict__ out,
                      int n_pairs)     // (B/2)*16
{
    extern __shared__ float2 gsm[];    // [(w+2)*16 + n] : bank pair = 2n

    // Stage grids (N,C,W) -> transposed padded smem. Zeros outside [0,W).
    for (int j = threadIdx.x; j < PADW * NLVL; j += TPB) {
        int n = j & (NLVL - 1);
        int w = (j >> 4) - 2;
        float c0 = 0.f, c1 = 0.f;
        if ((unsigned)w < (unsigned)WIDTH) {
            c0 = grids[(n * 2 + 0) * WIDTH + w];
            c1 = grids[(n * 2 + 1) * WIDTH + w];
        }
        gsm[j] = make_float2(c0, c1);
    }
    __syncthreads();

    const int gtid   = blockIdx.x * TPB + threadIdx.x;
    const int stride = gridDim.x * TPB;       // multiple of 16
    const int n      = gtid & (NLVL - 1);

    // Per-level constants in registers for the whole kernel.
    const u64 G00 = bc(G[  0 + n]), G01 = bc(G[ 16 + n]), G02 = bc(G[ 32 + n]);
    const u64 G10 = bc(G[ 48 + n]), G11 = bc(G[ 64 + n]), G12 = bc(G[ 80 + n]);
    const u64 G20 = bc(G[ 96 + n]), G21 = bc(G[112 + n]), G22 = bc(G[128 + n]);
    const u64 H0  = bc(H[  0 + n]), H1  = bc(H[ 16 + n]), H2  = bc(H[ 32 + n]);

    // Packed sin-reduction constants.
    const u64 INV2PI = bc(0.15915494309189535f);
    const u64 MAGIC  = bc(12582912.0f);              // 1.5 * 2^23
    const u64 NPIA   = bc(-6.28125f);
    const u64 NPIB   = bc(-1.934051513671875e-3f);
    const u64 NPIC   = bc(-1.2556659e-6f);

    const float MAG499 = 12583411.0f;                // 12582912 + 499, exact

    u32 smbase;
    asm("{ .reg .u64 t; cvta.to.shared.u64 t, %1; cvt.u32.u64 %0, t; }"
        : "=r"(smbase) : "l"(gsm));
    // addr(tap0) = bits(bb)*128 + addrc   (0x4B400000*128 mod 2^32 = 0xA0000000)
    const u32 addrc = smbase + 128u + (u32)(n * 8) - 0xA0000000u;

    // ---- software pipeline: preload x for the first iteration ----
    float2 q0, q1, q2;
    {
        int p0 = (gtid < n_pairs) ? gtid : 0;
        const float2* xp = (const float2*)(x + 6 * (p0 >> 4));
        q0 = xp[0]; q1 = xp[1]; q2 = xp[2];
    }

    for (int p = gtid; p < n_pairs; p += stride) {
        // ---- prefetch next iteration's x ----
        int pn = p + stride;
        int gn = ((pn < n_pairs) ? pn : p) >> 4;
        const float2* xn = (const float2*)(x + 6 * gn);
        float2 r0 = xn[0], r1 = xn[1], r2 = xn[2];

        // current pair: samples 2g (A), 2g+1 (B)
        u64 X0 = pk(q0.x, q1.y);
        u64 X1 = pk(q0.y, q2.x);
        u64 X2 = pk(q1.x, q2.y);

        u64 a0 = f2fma(X0, G00, f2fma(X1, G10, f2fma(X2, G20, H0)));
        u64 a1 = f2fma(X0, G01, f2fma(X1, G11, f2fma(X2, G21, H1)));
        u64 a2 = f2fma(X0, G02, f2fma(X1, G12, f2fma(X2, G22, H2)));

        // accurate packed reduction to [-pi,pi], then MUFU sin
        u64 rr0 = pred2pi(a0, INV2PI, MAGIC, NPIA, NPIB, NPIC);
        u64 rr1 = pred2pi(a1, INV2PI, MAGIC, NPIA, NPIB, NPIC);
        u64 rr2 = pred2pi(a2, INV2PI, MAGIC, NPIA, NPIB, NPIC);
        float r0A, r0B, r1A, r1B, r2A, r2B;
        upk(r0A, r0B, rr0); upk(r1A, r1B, rr1); upk(r2A, r2B, rr2);

        float gxA = hwsin(r0A) * hwsin(r1A) * hwsin(r2A);
        float gxB = hwsin(r0B) * hwsin(r1B) * hwsin(r2B);

        // fused ix chain: ix = 500*gx + 499.5
        float bbA = fmaf(gxA, 500.0f, MAG499);        // MAGIC + floor(ix)
        float bbB = fmaf(gxB, 500.0f, MAG499);
        float xfA = bbA - 12582912.0f;                // float(base)
        float xfB = bbB - 12582912.0f;
        float tA  = fmaf(gxA, 500.0f, 499.5f - xfA);  // t = ix - base
        float tB  = fmaf(gxB, 500.0f, 499.5f - xfB);

        // ---- issue all 8 tap loads up front ----
        const u32 adA = __float_as_uint(bbA) * 128u + addrc;
        const u32 adB = __float_as_uint(bbB) * 128u + addrc;
        float a0x,a0y,a1x,a1y,a2x,a2y,a3x,a3y;
        float b0x,b0y,b1x,b1y,b2x,b2y,b3x,b3y;
        asm("ld.shared.v2.f32 {%0,%1},[%2];"     : "=f"(a0x), "=f"(a0y) : "r"(adA));
        asm("ld.shared.v2.f32 {%0,%1},[%2+128];" : "=f"(a1x), "=f"(a1y) : "r"(adA));
        asm("ld.shared.v2.f32 {%0,%1},[%2+256];" : "=f"(a2x), "=f"(a2y) : "r"(adA));
        asm("ld.shared.v2.f32 {%0,%1},[%2+384];" : "=f"(a3x), "=f"(a3y) : "r"(adA));
        asm("ld.shared.v2.f32 {%0,%1},[%2];"     : "=f"(b0x), "=f"(b0y) : "r"(adB));
        asm("ld.shared.v2.f32 {%0,%1},[%2+128];" : "=f"(b1x), "=f"(b1y) : "r"(adB));
        asm("ld.shared.v2.f32 {%0,%1},[%2+256];" : "=f"(b2x), "=f"(b2y) : "r"(adB));
        asm("ld.shared.v2.f32 {%0,%1},[%2+384];" : "=f"(b3x), "=f"(b3y) : "r"(adB));

        // ---- scalar cubic weights, immediate-form FFMA (rt=1, no const regs) ----
        float paA = fmaf(-0.75f, tA, 1.5f);  paA = fmaf(paA, tA, -0.75f);
        float w0A = paA * tA;
        float pbA = fmaf(1.25f, tA, -2.25f);
        float w1A = fmaf(pbA * tA, tA, 1.0f);
        float pcA = fmaf(-1.25f, tA, 1.5f);  pcA = fmaf(pcA, tA, 0.75f);
        float w2A = pcA * tA;
        float pdA = fmaf(0.75f, tA, -0.75f);
        float w3A = pdA * tA * tA;

        float paB = fmaf(-0.75f, tB, 1.5f);  paB = fmaf(paB, tB, -0.75f);
        float w0B = paB * tB;
        float pbB = fmaf(1.25f, tB, -2.25f);
        float w1B = fmaf(pbB * tB, tB, 1.0f);
        float pcB = fmaf(-1.25f, tB, 1.5f);  pcB = fmaf(pcB, tB, 0.75f);
        float w2B = pcB * tB;
        float pdB = fmaf(0.75f, tB, -0.75f);
        float w3B = pdB * tB * tB;

        float accA0 = fmaf(a0x, w0A, fmaf(a1x, w1A, fmaf(a2x, w2A, a3x * w3A)));
        float accA1 = fmaf(a0y, w0A, fmaf(a1y, w1A, fmaf(a2y, w2A, a3y * w3A)));
        float accB0 = fmaf(b0x, w0B, fmaf(b1x, w1B, fmaf(b2x, w2B, b3x * w3B)));
        float accB1 = fmaf(b0y, w0B, fmaf(b1y, w1B, fmaf(b2y, w2B, b3y * w3B)));

        const int iA = 2 * p - n;             // out float2 index = s*16 + n
        out[iA]        = make_float2(accA0, accA1);
        out[iA + NLVL] = make_float2(accB0, accB1);

        // rotate pipeline
        q0 = r0; q1 = r1; q2 = r2;
    }
}

extern "C" void kernel_launch(void* const* d_in, const int* in_sizes, int n_in,
                              void* d_out, int out_size)
{
    const float* x     = (const float*)d_in[0];
    const float* grids = (const float*)d_in[1];
    const float* G     = (const float*)d_in[2];
    const float* H     = (const float*)d_in[3];
    (void)n_in; (void)out_size;

    const int B       = in_sizes[0] / 3;
    const int n_pairs = (B / 2) * NLVL;

    const int smem_bytes = PADW * NLVL * (int)sizeof(float2);   // 128512

    cudaFuncSetAttribute(trig_hash_kernel,
                         cudaFuncAttributeMaxDynamicSharedMemorySize, smem_bytes);

    int sm_count = 148;
    cudaDeviceGetAttribute(&sm_count, cudaDevAttrMultiProcessorCount, 0);

    trig_hash_kernel<<<sm_count, TPB, smem_bytes>>>(
        x, grids, G, H, (float2*)d_out, n_pairs);
}